// round 15
// baseline (speedup 1.0000x reference)
#include <cuda_runtime.h>
#include <cuda_bf16.h>
#include <math.h>
#include <stdint.h>

#define BB   8
#define CC   128
#define HH   56
#define WW   56
#define HWP  3136
#define REDC 32
#define GRP  8
#define KK   49
#define OCH  392
#define HID  512
#define NPIX 25088

// scratch
__device__ float g_inv[(size_t)NPIX * CC];
// weights pre-permuted into mma B-fragment layout
__device__ uint4 g_w1f[8 * 8 * 8 * 32];
__device__ uint4 g_w2f[8 * 4 * 16 * 32];

// ======================== helpers ========================
__device__ __forceinline__ uint32_t smem_to_u32(const void* p) {
    uint32_t a;
    asm("{ .reg .u64 t; cvta.to.shared.u64 t, %1; cvt.u32.u64 %0, t; }"
        : "=r"(a) : "l"(p));
    return a;
}
__device__ __forceinline__ void ldsm4(uint32_t r[4], uint32_t addr) {
    asm volatile("ldmatrix.sync.aligned.m8n8.x4.shared.b16 {%0,%1,%2,%3}, [%4];"
        : "=r"(r[0]), "=r"(r[1]), "=r"(r[2]), "=r"(r[3]) : "r"(addr));
}
__device__ __forceinline__ void mma16816(float c[4], const uint32_t a[4],
                                         uint32_t b0, uint32_t b1) {
    asm volatile(
        "mma.sync.aligned.m16n8k16.row.col.f32.bf16.bf16.f32 "
        "{%0,%1,%2,%3}, {%4,%5,%6,%7}, {%8,%9}, {%0,%1,%2,%3};"
        : "+f"(c[0]), "+f"(c[1]), "+f"(c[2]), "+f"(c[3])
        : "r"(a[0]), "r"(a[1]), "r"(a[2]), "r"(a[3]), "r"(b0), "r"(b1));
}
__device__ __forceinline__ void split_pack(float v0, float v1, uint32_t& hi, uint32_t& lo) {
    __nv_bfloat16 h0 = __float2bfloat16(v0);
    __nv_bfloat16 h1 = __float2bfloat16(v1);
    __nv_bfloat16 l0 = __float2bfloat16(v0 - __bfloat162float(h0));
    __nv_bfloat16 l1 = __float2bfloat16(v1 - __bfloat162float(h1));
    __nv_bfloat162 hp; hp.x = h0; hp.y = h1;
    __nv_bfloat162 lp; lp.x = l0; lp.y = l1;
    hi = *(uint32_t*)&hp; lo = *(uint32_t*)&lp;
}

// permute one weight element into mma B-fragment layout (kernP body)
__device__ __forceinline__ void permute_one(int idx, const float* __restrict__ w1,
                                            const float* __restrict__ w2)
{
    float v00, v01, v10, v11;
    uint4* dst;
    if (idx < 16384) {
        int l  = idx & 31;
        int nt = (idx >> 5) & 7;
        int kt = (idx >> 8) & 7;
        int c  = idx >> 11;
        int n = c * 64 + nt * 8 + (l >> 2);
        int k = kt * 16 + (l & 3) * 2;
        const float* p = w1 + (size_t)n * 128 + k;
        v00 = p[0]; v01 = p[1]; v10 = p[8]; v11 = p[9];
        dst = g_w1f + idx;
    } else {
        int i2 = idx - 16384;
        int l   = i2 & 31;
        int nt  = (i2 >> 5) & 15;
        int kt2 = (i2 >> 9) & 3;
        int nb  = i2 >> 11;
        int n = nt * 8 + (l >> 2);
        int k = nb * 64 + kt2 * 16 + (l & 3) * 2;
        const float* p = w2 + (size_t)n * 512 + k;
        v00 = p[0]; v01 = p[1]; v10 = p[8]; v11 = p[9];
        dst = g_w2f + i2;
    }
    uint32_t h0, l0, h1, l1;
    split_pack(v00, v01, h0, l0);
    split_pack(v10, v11, h1, l1);
    *dst = make_uint4(h0, h1, l0, l1);
}

// ---------------------------------------------------------------------------
// kernFI: fused conv1+BN+ReLU -> conv2 (per group) -> involution.
// Blocks [0,448): conv/involution work. Blocks [448,595): weight permute.
// ---------------------------------------------------------------------------
#define F_TS 0
#define F_A  1920
#define F_XS F_A
#define F_WG F_A
#define F_HA (F_A + 2940)
#define F_TOT (F_A + 2940 + 7232)
#define SMEM_F (F_TOT * 4)
#define NPERM_BLK 147   // ceil(32768 / 224)

__global__ __launch_bounds__(224, 4) void kernFI(
    const float* __restrict__ x,
    const float* __restrict__ c1w, const float* __restrict__ c1b,
    const float* __restrict__ bng, const float* __restrict__ bnb,
    const float* __restrict__ bnm, const float* __restrict__ bnv,
    const float* __restrict__ c2w, const float* __restrict__ c2b,
    const float* __restrict__ w1,  const float* __restrict__ w2)
{
    const int tid = threadIdx.x;

    if (blockIdx.x >= BB * HH) {
        int idx = (blockIdx.x - BB * HH) * 224 + tid;
        if (idx < 32768) permute_one(idx, w1, w2);
        return;
    }

    extern __shared__ float smf[];
    float* ts = smf + F_TS;
    float* xs = smf + F_XS;
    float* wg = smf + F_WG;
    float* ha = smf + F_HA;

    const int bIdx = blockIdx.x / 56;
    const int h    = blockIdx.x % 56;
    const float* xb = x + (size_t)bIdx * CC * HWP;

    // ---- stage xs[128][60]: row h, all 128 channels ----
    for (int i = tid; i < 128 * 14; i += 224) {
        int c = i / 14, f = i % 14;
        *(float4*)&xs[c * 60 + f * 4] =
            *(const float4*)(xb + (size_t)c * HWP + h * 56 + f * 4);
    }
    __syncthreads();

    // ---- conv1 (128->32) + BN + ReLU -> ts[32][60] ----
    {
        const int wh = tid % 28, rg = tid / 28;
        const int w0 = wh * 2, r0 = rg * 4;
        float a[4][2] = {{0.f,0.f},{0.f,0.f},{0.f,0.f},{0.f,0.f}};
        #pragma unroll 4
        for (int k4 = 0; k4 < 32; k4++) {
            float wv[4][4];
            #pragma unroll
            for (int q = 0; q < 4; q++)
                *(float4*)wv[q] = *(const float4*)(c1w + (size_t)(r0 + q) * 128 + k4 * 4);
            #pragma unroll
            for (int kk = 0; kk < 4; kk++) {
                float x0 = xs[(k4 * 4 + kk) * 60 + w0];
                float x1 = xs[(k4 * 4 + kk) * 60 + w0 + 1];
                #pragma unroll
                for (int q = 0; q < 4; q++) {
                    a[q][0] = fmaf(wv[q][kk], x0, a[q][0]);
                    a[q][1] = fmaf(wv[q][kk], x1, a[q][1]);
                }
            }
        }
        #pragma unroll
        for (int q = 0; q < 4; q++) {
            int r = r0 + q;
            float sc = bng[r] * rsqrtf(bnv[r] + 1e-5f);
            float sh = (c1b[r] - bnm[r]) * sc + bnb[r];
            ts[r * 60 + w0]     = fmaxf(fmaf(a[q][0], sc, sh), 0.f);
            ts[r * 60 + w0 + 1] = fmaxf(fmaf(a[q][1], sc, sh), 0.f);
        }
    }
    __syncthreads();   // ts ready; xs dead

    const int oq  = tid / 14;
    const int wq4 = (tid % 14) * 4;
    const int ci  = tid & 15;
    const int w0i = (tid >> 4) * 4;
    const size_t pxb = (size_t)bIdx * HWP + (size_t)h * 56;

    for (int g = 0; g < 8; g++) {
        // ---- conv2: this group's 49 oc x 56 px -> wg ----
        if (oq < 13) {
            int ocl = oq * 4 < 45 ? oq * 4 : 45;
            float a[4][4];
            #pragma unroll
            for (int q = 0; q < 4; q++)
                #pragma unroll
                for (int i = 0; i < 4; i++) a[q][i] = 0.f;
            #pragma unroll
            for (int r4 = 0; r4 < 8; r4++) {
                float wv[4][4];
                #pragma unroll
                for (int q = 0; q < 4; q++)
                    *(float4*)wv[q] =
                        *(const float4*)(c2w + (size_t)(g * 49 + ocl + q) * 32 + r4 * 4);
                #pragma unroll
                for (int kk = 0; kk < 4; kk++) {
                    float tv[4];
                    *(float4*)tv = *(float4*)&ts[(r4 * 4 + kk) * 60 + wq4];
                    #pragma unroll
                    for (int q = 0; q < 4; q++)
                        #pragma unroll
                        for (int i = 0; i < 4; i++)
                            a[q][i] = fmaf(wv[q][kk], tv[i], a[q][i]);
                }
            }
            #pragma unroll
            for (int q = 0; q < 4; q++) {
                float bb = c2b[g * 49 + ocl + q];
                *(float4*)&wg[(ocl + q) * 60 + wq4] =
                    make_float4(a[q][0] + bb, a[q][1] + bb, a[q][2] + bb, a[q][3] + bb);
            }
        }
        // ---- halo: 16 ch x 7 rows x 64 cols (zero-padded) ----
        for (int t = tid; t < 16 * 448; t += 224) {
            int j = t & 63;
            int r = (t >> 6) % 7;
            int c = t / 448;
            int h2 = h + r - 3, w2 = j - 3;
            float v = 0.f;
            if ((unsigned)h2 < 56u && (unsigned)w2 < 56u)
                v = xb[(size_t)(g * 16 + c) * HWP + h2 * 56 + w2];
            ha[c * 452 + r * 64 + j] = v;
        }
        __syncthreads();

        // ---- involution: 1 ch x 4 w per thread ----
        {
            float acc[4] = {0.f, 0.f, 0.f, 0.f};
            const float* hb = ha + ci * 452;
            #pragma unroll
            for (int kh = 0; kh < 7; kh++) {
                float xr[12];
                *(float4*)&xr[0] = *(float4*)&hb[kh * 64 + w0i];
                *(float4*)&xr[4] = *(float4*)&hb[kh * 64 + w0i + 4];
                *(float4*)&xr[8] = *(float4*)&hb[kh * 64 + w0i + 8];
                #pragma unroll
                for (int kw = 0; kw < 7; kw++) {
                    float4 wv = *(float4*)&wg[(kh * 7 + kw) * 60 + w0i];
                    acc[0] = fmaf(wv.x, xr[kw],     acc[0]);
                    acc[1] = fmaf(wv.y, xr[kw + 1], acc[1]);
                    acc[2] = fmaf(wv.z, xr[kw + 2], acc[2]);
                    acc[3] = fmaf(wv.w, xr[kw + 3], acc[3]);
                }
            }
            #pragma unroll
            for (int wi = 0; wi < 4; wi++)
                g_inv[(pxb + w0i + wi) * CC + g * 16 + ci] = acc[wi];
        }
        __syncthreads();
    }
}

// ---------------------------------------------------------------------------
// kernM v6: 64-px CTA, 4 warps, 4 CTAs/SM (regs<=128, smem 55.8KB x4 fits).
// ---------------------------------------------------------------------------
#define MS_B1  0
#define MS_B2  2048
#define MS_YSH 2560
#define MS_YSL (MS_YSH + 17408)
#define MS_HSH (MS_YSL + 17408)
#define MS_HSL (MS_HSH + 9216)
#define SMEM_M (MS_HSL + 9216)

__global__ __launch_bounds__(128, 4) void kernM(
    const float* __restrict__ x,
    const float* __restrict__ b1, const float* __restrict__ b2,
    const float* __restrict__ lnw, const float* __restrict__ lnb,
    float* __restrict__ out)
{
    extern __shared__ char smraw[];
    const uint32_t sb = smem_to_u32(smraw);
    float* b1s = (float*)(smraw + MS_B1);
    float* b2s = (float*)(smraw + MS_B2);

    const int tid = threadIdx.x;
    const int wid = tid >> 5;
    const int l   = tid & 31;
    const size_t p0 = (size_t)blockIdx.x * 64;

    for (int t = tid; t < 512; t += 128) b1s[t] = b1[t];
    if (tid < 128) b2s[tid] = b2[tid];

    // ---- LN + bf16 hi/lo staging of ys ----
    {
        const int px = tid >> 1, half = tid & 1;
        const float* src = g_inv + (p0 + px) * CC + half * 64;
        float s = 0.f, s2 = 0.f;
        #pragma unroll 4
        for (int i = 0; i < 64; i += 4) {
            float4 v = *(const float4*)(src + i);
            s += v.x + v.y + v.z + v.w;
            s2 = fmaf(v.x, v.x, s2); s2 = fmaf(v.y, v.y, s2);
            s2 = fmaf(v.z, v.z, s2); s2 = fmaf(v.w, v.w, s2);
        }
        s  += __shfl_xor_sync(0xffffffffu, s, 1);
        s2 += __shfl_xor_sync(0xffffffffu, s2, 1);
        float mu  = s * (1.f / 128.f);
        float var = s2 * (1.f / 128.f) - mu * mu;
        float rs  = rsqrtf(var + 1e-6f);
        #pragma unroll 4
        for (int i = 0; i < 64; i += 2) {
            int k = half * 64 + i;
            float y0 = (src[i]     - mu) * rs * lnw[k]     + lnb[k];
            float y1 = (src[i + 1] - mu) * rs * lnw[k + 1] + lnb[k + 1];
            uint32_t hi, lo;
            split_pack(y0, y1, hi, lo);
            *(uint32_t*)(smraw + MS_YSH + px * 272 + k * 2) = hi;
            *(uint32_t*)(smraw + MS_YSL + px * 272 + k * 2) = lo;
        }
    }
    __syncthreads();

    const int rg = wid >> 1;
    const int cg = wid & 1;
    const int r_l   = l & 15;
    const int koffB = (l >> 4) * 16;

    uint32_t aBH[2], aBL[2];
    #pragma unroll
    for (int mt = 0; mt < 2; mt++) {
        uint32_t ro = (rg * 32 + mt * 16 + r_l) * 272 + koffB;
        aBH[mt] = sb + MS_YSH + ro;
        aBL[mt] = sb + MS_YSL + ro;
    }
    uint32_t hBH[2], hBL[2];
    #pragma unroll
    for (int mt = 0; mt < 2; mt++) {
        uint32_t ro = (rg * 32 + mt * 16 + r_l) * 144 + koffB;
        hBH[mt] = sb + MS_HSH + ro;
        hBL[mt] = sb + MS_HSL + ro;
    }

    float acc2[16][4];
    #pragma unroll
    for (int n = 0; n < 16; n++)
        #pragma unroll
        for (int q = 0; q < 4; q++) acc2[n][q] = 0.f;

    const uint4* w1p = g_w1f + l;
    const uint4* w2p = g_w2f + l;

    for (int nb = 0; nb < 8; nb++) {
        const int j0 = nb * 64;
        const uint4* b1w = w1p + (size_t)(nb * 8 * 8 + cg * 4) * 32;
        const uint4* b2w = w2p + (size_t)(nb * 4 * 16 + cg * 8) * 32;

        // ---- GEMM1: double-buffered weight fragments ----
        float c1[8][4];
        #pragma unroll
        for (int n = 0; n < 8; n++)
            #pragma unroll
            for (int q = 0; q < 4; q++) c1[n][q] = 0.f;

        uint4 wc[4];
        #pragma unroll
        for (int i = 0; i < 4; i++) wc[i] = b1w[(size_t)i * 32];

        #pragma unroll
        for (int kt = 0; kt < 8; kt++) {
            uint32_t ah0[4], ah1[4], al0[4], al1[4];
            ldsm4(ah0, aBH[0] + kt * 32);
            ldsm4(ah1, aBH[1] + kt * 32);
            ldsm4(al0, aBL[0] + kt * 32);
            ldsm4(al1, aBL[1] + kt * 32);
            uint4 wn[4];
            if (kt < 7) {
                #pragma unroll
                for (int i = 0; i < 4; i++)
                    wn[i] = b1w[(size_t)((kt + 1) * 8 + i) * 32];
            }
            #pragma unroll
            for (int nt = 0; nt < 4; nt++) {
                mma16816(c1[nt],     ah0, wc[nt].x, wc[nt].y);
                mma16816(c1[nt],     ah0, wc[nt].z, wc[nt].w);
                mma16816(c1[nt],     al0, wc[nt].x, wc[nt].y);
                mma16816(c1[4 + nt], ah1, wc[nt].x, wc[nt].y);
                mma16816(c1[4 + nt], ah1, wc[nt].z, wc[nt].w);
                mma16816(c1[4 + nt], al1, wc[nt].x, wc[nt].y);
            }
            #pragma unroll
            for (int i = 0; i < 4; i++) wc[i] = wn[i];
        }

        // ---- bias + exact GELU -> hs ----
        #pragma unroll
        for (int mt = 0; mt < 2; mt++) {
            int row = rg * 32 + mt * 16 + (l >> 2);
            #pragma unroll
            for (int nt = 0; nt < 4; nt++) {
                int jc = cg * 32 + nt * 8 + (l & 3) * 2;
                float2 bv = *(const float2*)&b1s[j0 + jc];
                float v0 = c1[mt * 4 + nt][0] + bv.x;
                float v1 = c1[mt * 4 + nt][1] + bv.y;
                float v2 = c1[mt * 4 + nt][2] + bv.x;
                float v3 = c1[mt * 4 + nt][3] + bv.y;
                float g0 = 0.5f * v0 * (1.f + erff(v0 * 0.70710678118654752f));
                float g1 = 0.5f * v1 * (1.f + erff(v1 * 0.70710678118654752f));
                float g2 = 0.5f * v2 * (1.f + erff(v2 * 0.70710678118654752f));
                float g3 = 0.5f * v3 * (1.f + erff(v3 * 0.70710678118654752f));
                uint32_t hi, lo;
                split_pack(g0, g1, hi, lo);
                *(uint32_t*)(smraw + MS_HSH + row * 144 + jc * 2) = hi;
                *(uint32_t*)(smraw + MS_HSL + row * 144 + jc * 2) = lo;
                split_pack(g2, g3, hi, lo);
                *(uint32_t*)(smraw + MS_HSH + (row + 8) * 144 + jc * 2) = hi;
                *(uint32_t*)(smraw + MS_HSL + (row + 8) * 144 + jc * 2) = lo;
            }
        }
        __syncthreads();

        // ---- GEMM2: double-buffered in half-kt groups of 4 fragments ----
        uint4 w2c[4];
        #pragma unroll
        for (int i = 0; i < 4; i++) w2c[i] = b2w[(size_t)i * 32];

        #pragma unroll
        for (int kt2 = 0; kt2 < 4; kt2++) {
            uint32_t a0h[4], a1h[4], a0l[4], a1l[4];
            ldsm4(a0h, hBH[0] + kt2 * 32);
            ldsm4(a1h, hBH[1] + kt2 * 32);
            ldsm4(a0l, hBL[0] + kt2 * 32);
            ldsm4(a1l, hBL[1] + kt2 * 32);

            uint4 wnA[4];
            #pragma unroll
            for (int i = 0; i < 4; i++)
                wnA[i] = b2w[(size_t)(kt2 * 16 + 4 + i) * 32];

            #pragma unroll
            for (int nt = 0; nt < 4; nt++) {
                mma16816(acc2[nt],     a0h, w2c[nt].x, w2c[nt].y);
                mma16816(acc2[nt],     a0h, w2c[nt].z, w2c[nt].w);
                mma16816(acc2[nt],     a0l, w2c[nt].x, w2c[nt].y);
                mma16816(acc2[8 + nt], a1h, w2c[nt].x, w2c[nt].y);
                mma16816(acc2[8 + nt], a1h, w2c[nt].z, w2c[nt].w);
                mma16816(acc2[8 + nt], a1l, w2c[nt].x, w2c[nt].y);
            }
            uint4 wnB[4];
            if (kt2 < 3) {
                #pragma unroll
                for (int i = 0; i < 4; i++)
                    wnB[i] = b2w[(size_t)((kt2 + 1) * 16 + i) * 32];
            }
            #pragma unroll
            for (int nt = 0; nt < 4; nt++) {
                mma16816(acc2[4 + nt],  a0h, wnA[nt].x, wnA[nt].y);
                mma16816(acc2[4 + nt],  a0h, wnA[nt].z, wnA[nt].w);
                mma16816(acc2[4 + nt],  a0l, wnA[nt].x, wnA[nt].y);
                mma16816(acc2[12 + nt], a1h, wnA[nt].x, wnA[nt].y);
                mma16816(acc2[12 + nt], a1h, wnA[nt].z, wnA[nt].w);
                mma16816(acc2[12 + nt], a1l, wnA[nt].x, wnA[nt].y);
            }
            #pragma unroll
            for (int i = 0; i < 4; i++) w2c[i] = wnB[i];
        }
        __syncthreads();
    }

    // ---- epilogue: + b2 + x, NCHW store ----
    #pragma unroll
    for (int mt = 0; mt < 2; mt++) {
        #pragma unroll
        for (int half = 0; half < 2; half++) {
            int row = rg * 32 + mt * 16 + (l >> 2) + half * 8;
            size_t gpx = p0 + row;
            size_t bI = gpx / HWP, hw = gpx % HWP;
            const float* xb = x + bI * CC * HWP + hw;
            float* ob = out + bI * CC * HWP + hw;
            #pragma unroll
            for (int ntp = 0; ntp < 8; ntp++) {
                int c = cg * 64 + ((ntp < 4) ? ntp * 8 : 32 + (ntp - 4) * 8) + (l & 3) * 2;
                int ai = mt * 8 + ((ntp < 4) ? ntp : 4 + (ntp - 4));
                ob[(size_t)c * HWP] =
                    acc2[ai][half * 2] + b2s[c] + xb[(size_t)c * HWP];
                ob[(size_t)(c + 1) * HWP] =
                    acc2[ai][half * 2 + 1] + b2s[c + 1] + xb[(size_t)(c + 1) * HWP];
            }
        }
    }
}

// ---------------------------------------------------------------------------
extern "C" void kernel_launch(void* const* d_in, const int* in_sizes, int n_in,
                              void* d_out, int out_size)
{
    const float* x   = (const float*)d_in[0];
    const float* c1w = (const float*)d_in[1];
    const float* c1b = (const float*)d_in[2];
    const float* bng = (const float*)d_in[3];
    const float* bnb = (const float*)d_in[4];
    const float* bnm = (const float*)d_in[5];
    const float* bnv = (const float*)d_in[6];
    const float* c2w = (const float*)d_in[7];
    const float* c2b = (const float*)d_in[8];
    const float* lnw = (const float*)d_in[9];
    const float* lnb = (const float*)d_in[10];
    const float* w1  = (const float*)d_in[11];
    const float* b1  = (const float*)d_in[12];
    const float* w2  = (const float*)d_in[13];
    const float* b2  = (const float*)d_in[14];
    float* out = (float*)d_out;

    cudaFuncSetAttribute(kernFI, cudaFuncAttributeMaxDynamicSharedMemorySize, SMEM_F);
    cudaFuncSetAttribute(kernM, cudaFuncAttributeMaxDynamicSharedMemorySize, SMEM_M);

    kernFI<<<BB * HH + NPERM_BLK, 224, SMEM_F>>>(
        x, c1w, c1b, bng, bnb, bnm, bnv, c2w, c2b, w1, w2);
    kernM<<<NPIX / 64, 128, SMEM_M>>>(x, b1, b2, lnw, lnb, out);
}

// round 16
// speedup vs baseline: 1.1810x; 1.1810x over previous
#include <cuda_runtime.h>
#include <cuda_bf16.h>
#include <math.h>
#include <stdint.h>

#define BB   8
#define CC   128
#define HH   56
#define WW   56
#define HWP  3136
#define REDC 32
#define GRP  8
#define KK   49
#define OCH  392
#define HID  512
#define NPIX 25088

// scratch
__device__ float g_inv[(size_t)NPIX * CC];
// weights pre-permuted into mma B-fragment layout
__device__ uint4 g_w1f[8 * 8 * 8 * 32];
__device__ uint4 g_w2f[8 * 4 * 16 * 32];

// ======================== helpers ========================
__device__ __forceinline__ uint32_t smem_to_u32(const void* p) {
    uint32_t a;
    asm("{ .reg .u64 t; cvta.to.shared.u64 t, %1; cvt.u32.u64 %0, t; }"
        : "=r"(a) : "l"(p));
    return a;
}
__device__ __forceinline__ void ldsm4(uint32_t r[4], uint32_t addr) {
    asm volatile("ldmatrix.sync.aligned.m8n8.x4.shared.b16 {%0,%1,%2,%3}, [%4];"
        : "=r"(r[0]), "=r"(r[1]), "=r"(r[2]), "=r"(r[3]) : "r"(addr));
}
__device__ __forceinline__ void mma16816(float c[4], const uint32_t a[4],
                                         uint32_t b0, uint32_t b1) {
    asm volatile(
        "mma.sync.aligned.m16n8k16.row.col.f32.bf16.bf16.f32 "
        "{%0,%1,%2,%3}, {%4,%5,%6,%7}, {%8,%9}, {%0,%1,%2,%3};"
        : "+f"(c[0]), "+f"(c[1]), "+f"(c[2]), "+f"(c[3])
        : "r"(a[0]), "r"(a[1]), "r"(a[2]), "r"(a[3]), "r"(b0), "r"(b1));
}
__device__ __forceinline__ void split_pack(float v0, float v1, uint32_t& hi, uint32_t& lo) {
    __nv_bfloat16 h0 = __float2bfloat16(v0);
    __nv_bfloat16 h1 = __float2bfloat16(v1);
    __nv_bfloat16 l0 = __float2bfloat16(v0 - __bfloat162float(h0));
    __nv_bfloat16 l1 = __float2bfloat16(v1 - __bfloat162float(h1));
    __nv_bfloat162 hp; hp.x = h0; hp.y = h1;
    __nv_bfloat162 lp; lp.x = l0; lp.y = l1;
    hi = *(uint32_t*)&hp; lo = *(uint32_t*)&lp;
}

// ---------------------------------------------------------------------------
// kernP: permute w1/w2 into bf16 hi/lo mma fragments (separate, as in R13)
// ---------------------------------------------------------------------------
__global__ __launch_bounds__(256) void kernP(const float* __restrict__ w1,
                                             const float* __restrict__ w2)
{
    int idx = blockIdx.x * 256 + threadIdx.x;   // [0, 32768)
    float v00, v01, v10, v11;
    uint4* dst;
    if (idx < 16384) {
        int l  = idx & 31;
        int nt = (idx >> 5) & 7;
        int kt = (idx >> 8) & 7;
        int c  = idx >> 11;
        int n = c * 64 + nt * 8 + (l >> 2);
        int k = kt * 16 + (l & 3) * 2;
        const float* p = w1 + (size_t)n * 128 + k;
        v00 = p[0]; v01 = p[1]; v10 = p[8]; v11 = p[9];
        dst = g_w1f + idx;
    } else {
        int i2 = idx - 16384;
        int l   = i2 & 31;
        int nt  = (i2 >> 5) & 15;
        int kt2 = (i2 >> 9) & 3;
        int nb  = i2 >> 11;
        int n = nt * 8 + (l >> 2);
        int k = nb * 64 + kt2 * 16 + (l & 3) * 2;
        const float* p = w2 + (size_t)n * 512 + k;
        v00 = p[0]; v01 = p[1]; v10 = p[8]; v11 = p[9];
        dst = g_w2f + i2;
    }
    uint32_t h0, l0, h1, l1;
    split_pack(v00, v01, h0, l0);
    split_pack(v10, v11, h1, l1);
    *dst = make_uint4(h0, h1, l0, l1);
}

// ---------------------------------------------------------------------------
// kernFI v3: fused conv1+BN+ReLU -> conv2 -> involution, h-PAIR per block.
// Block = (b, hp), 448 threads, 2 CTAs/SM. Halo traffic halved vs v2.
// smem floats: ts[2][32][60] @0 (3840); region A @3840:
//   phase1: xs[128][60] (7680)
//   per-g : wg[2][49][60] (5880) @3840 ; halo[16][516] (8256) @9720
// total 17976 floats = 71904 B
// ---------------------------------------------------------------------------
#define F2_TS 0
#define F2_A  3840
#define F2_XS F2_A
#define F2_WG F2_A
#define F2_HA (F2_A + 5880)
#define F2_TOT (F2_A + 5880 + 8256)
#define SMEM_F2 (F2_TOT * 4)

__global__ __launch_bounds__(448, 2) void kernFI(
    const float* __restrict__ x,
    const float* __restrict__ c1w, const float* __restrict__ c1b,
    const float* __restrict__ bng, const float* __restrict__ bnb,
    const float* __restrict__ bnm, const float* __restrict__ bnv,
    const float* __restrict__ c2w, const float* __restrict__ c2b)
{
    extern __shared__ float smf[];
    float* ts = smf + F2_TS;   // [2][32][60]
    float* xs = smf + F2_XS;   // [128][60]
    float* wg = smf + F2_WG;   // [2][49][60]
    float* ha = smf + F2_HA;   // [16][516]

    const int bIdx = blockIdx.x / 28;
    const int hp   = blockIdx.x % 28;
    const int h0   = hp * 2;
    const int tid  = threadIdx.x;
    const float* xb = x + (size_t)bIdx * CC * HWP;

    // ---- phase A: for each of the 2 rows: stage xs, conv1+BN+ReLU -> ts ----
    const int wh = tid % 56;          // conv1: 1 px
    const int rq = tid / 56;          // 4 reduced-rows
    for (int rr = 0; rr < 2; rr++) {
        for (int i = tid; i < 128 * 14; i += 448) {
            int c = i / 14, f = i % 14;
            *(float4*)&xs[c * 60 + f * 4] =
                *(const float4*)(xb + (size_t)c * HWP + (h0 + rr) * 56 + f * 4);
        }
        __syncthreads();
        {
            int r0 = rq * 4;
            float a[4] = {0.f, 0.f, 0.f, 0.f};
            #pragma unroll 4
            for (int k4 = 0; k4 < 32; k4++) {
                float wv[4][4];
                #pragma unroll
                for (int q = 0; q < 4; q++)
                    *(float4*)wv[q] = *(const float4*)(c1w + (size_t)(r0 + q) * 128 + k4 * 4);
                #pragma unroll
                for (int kk = 0; kk < 4; kk++) {
                    float xv = xs[(k4 * 4 + kk) * 60 + wh];
                    #pragma unroll
                    for (int q = 0; q < 4; q++)
                        a[q] = fmaf(wv[q][kk], xv, a[q]);
                }
            }
            __syncthreads();   // xs reads done before next restage / wg alias
            #pragma unroll
            for (int q = 0; q < 4; q++) {
                int r = r0 + q;
                float sc = bng[r] * rsqrtf(bnv[r] + 1e-5f);
                float sh = (c1b[r] - bnm[r]) * sc + bnb[r];
                ts[rr * 1920 + r * 60 + wh] = fmaxf(fmaf(a[q], sc, sh), 0.f);
            }
        }
    }
    __syncthreads();   // ts fully ready; xs dead

    // conv2 map: oq(16) x rr(2) x wq(14); active oq<13
    const int oq   = tid / 28;
    const int rst  = tid % 28;
    const int c2rr = rst / 14;
    const int wq4  = (rst % 14) * 4;
    // involution map: ci(16) x rowi(2) x wqi(14)
    const int ci   = tid & 15;
    const int rst2 = tid >> 4;        // 0..27
    const int rowi = rst2 & 1;
    const int w0i  = (rst2 >> 1) * 4;

    for (int g = 0; g < 8; g++) {
        // ---- conv2: group g, 49 oc x 2 rows x 56 px -> wg ----
        if (oq < 13) {
            int ocl = oq * 4 < 45 ? oq * 4 : 45;
            float a[4][4];
            #pragma unroll
            for (int q = 0; q < 4; q++)
                #pragma unroll
                for (int i = 0; i < 4; i++) a[q][i] = 0.f;
            #pragma unroll
            for (int r4 = 0; r4 < 8; r4++) {
                float wv[4][4];
                #pragma unroll
                for (int q = 0; q < 4; q++)
                    *(float4*)wv[q] =
                        *(const float4*)(c2w + (size_t)(g * 49 + ocl + q) * 32 + r4 * 4);
                #pragma unroll
                for (int kk = 0; kk < 4; kk++) {
                    float tv[4];
                    *(float4*)tv = *(float4*)&ts[c2rr * 1920 + (r4 * 4 + kk) * 60 + wq4];
                    #pragma unroll
                    for (int q = 0; q < 4; q++)
                        #pragma unroll
                        for (int i = 0; i < 4; i++)
                            a[q][i] = fmaf(wv[q][kk], tv[i], a[q][i]);
                }
            }
            #pragma unroll
            for (int q = 0; q < 4; q++) {
                float bb = c2b[g * 49 + ocl + q];
                *(float4*)&wg[c2rr * 2940 + (ocl + q) * 60 + wq4] =
                    make_float4(a[q][0] + bb, a[q][1] + bb, a[q][2] + bb, a[q][3] + bb);
            }
        }
        // ---- halo: 16 ch x 8 rows x 64 cols (zero-padded) ----
        for (int t = tid; t < 16 * 512; t += 448) {
            int j = t & 63;
            int r = (t >> 6) & 7;
            int c = t >> 9;
            int h2 = h0 + r - 3, w2 = j - 3;
            float v = 0.f;
            if ((unsigned)h2 < 56u && (unsigned)w2 < 56u)
                v = xb[(size_t)(g * 16 + c) * HWP + h2 * 56 + w2];
            ha[c * 516 + r * 64 + j] = v;
        }
        __syncthreads();

        // ---- involution: 1 ch x 1 row x 4 w per thread ----
        {
            float acc[4] = {0.f, 0.f, 0.f, 0.f};
            const float* hb = ha + ci * 516 + rowi * 64;
            const float* wb = wg + rowi * 2940;
            #pragma unroll
            for (int kh = 0; kh < 7; kh++) {
                float xr[12];
                *(float4*)&xr[0] = *(const float4*)&hb[kh * 64 + w0i];
                *(float4*)&xr[4] = *(const float4*)&hb[kh * 64 + w0i + 4];
                *(float4*)&xr[8] = *(const float4*)&hb[kh * 64 + w0i + 8];
                #pragma unroll
                for (int kw = 0; kw < 7; kw++) {
                    float4 wv = *(const float4*)&wb[(kh * 7 + kw) * 60 + w0i];
                    acc[0] = fmaf(wv.x, xr[kw],     acc[0]);
                    acc[1] = fmaf(wv.y, xr[kw + 1], acc[1]);
                    acc[2] = fmaf(wv.z, xr[kw + 2], acc[2]);
                    acc[3] = fmaf(wv.w, xr[kw + 3], acc[3]);
                }
            }
            size_t pxb = (size_t)bIdx * HWP + (size_t)(h0 + rowi) * 56;
            #pragma unroll
            for (int wi = 0; wi < 4; wi++)
                g_inv[(pxb + w0i + wi) * CC + g * 16 + ci] = acc[wi];
        }
        __syncthreads();
    }
}

// ---------------------------------------------------------------------------
// kernM v5 (R13 config): 64-px CTA, 4 warps, lb(128,3), double-buffered.
// ---------------------------------------------------------------------------
#define MS_B1  0
#define MS_B2  2048
#define MS_YSH 2560
#define MS_YSL (MS_YSH + 17408)
#define MS_HSH (MS_YSL + 17408)
#define MS_HSL (MS_HSH + 9216)
#define SMEM_M (MS_HSL + 9216)

__global__ __launch_bounds__(128, 3) void kernM(
    const float* __restrict__ x,
    const float* __restrict__ b1, const float* __restrict__ b2,
    const float* __restrict__ lnw, const float* __restrict__ lnb,
    float* __restrict__ out)
{
    extern __shared__ char smraw[];
    const uint32_t sb = smem_to_u32(smraw);
    float* b1s = (float*)(smraw + MS_B1);
    float* b2s = (float*)(smraw + MS_B2);

    const int tid = threadIdx.x;
    const int wid = tid >> 5;
    const int l   = tid & 31;
    const size_t p0 = (size_t)blockIdx.x * 64;

    for (int t = tid; t < 512; t += 128) b1s[t] = b1[t];
    if (tid < 128) b2s[tid] = b2[tid];

    // ---- LN + bf16 hi/lo staging of ys ----
    {
        const int px = tid >> 1, half = tid & 1;
        const float* src = g_inv + (p0 + px) * CC + half * 64;
        float s = 0.f, s2 = 0.f;
        #pragma unroll 4
        for (int i = 0; i < 64; i += 4) {
            float4 v = *(const float4*)(src + i);
            s += v.x + v.y + v.z + v.w;
            s2 = fmaf(v.x, v.x, s2); s2 = fmaf(v.y, v.y, s2);
            s2 = fmaf(v.z, v.z, s2); s2 = fmaf(v.w, v.w, s2);
        }
        s  += __shfl_xor_sync(0xffffffffu, s, 1);
        s2 += __shfl_xor_sync(0xffffffffu, s2, 1);
        float mu  = s * (1.f / 128.f);
        float var = s2 * (1.f / 128.f) - mu * mu;
        float rs  = rsqrtf(var + 1e-6f);
        #pragma unroll 4
        for (int i = 0; i < 64; i += 2) {
            int k = half * 64 + i;
            float y0 = (src[i]     - mu) * rs * lnw[k]     + lnb[k];
            float y1 = (src[i + 1] - mu) * rs * lnw[k + 1] + lnb[k + 1];
            uint32_t hi, lo;
            split_pack(y0, y1, hi, lo);
            *(uint32_t*)(smraw + MS_YSH + px * 272 + k * 2) = hi;
            *(uint32_t*)(smraw + MS_YSL + px * 272 + k * 2) = lo;
        }
    }
    __syncthreads();

    const int rg = wid >> 1;
    const int cg = wid & 1;
    const int r_l   = l & 15;
    const int koffB = (l >> 4) * 16;

    uint32_t aBH[2], aBL[2];
    #pragma unroll
    for (int mt = 0; mt < 2; mt++) {
        uint32_t ro = (rg * 32 + mt * 16 + r_l) * 272 + koffB;
        aBH[mt] = sb + MS_YSH + ro;
        aBL[mt] = sb + MS_YSL + ro;
    }
    uint32_t hBH[2], hBL[2];
    #pragma unroll
    for (int mt = 0; mt < 2; mt++) {
        uint32_t ro = (rg * 32 + mt * 16 + r_l) * 144 + koffB;
        hBH[mt] = sb + MS_HSH + ro;
        hBL[mt] = sb + MS_HSL + ro;
    }

    float acc2[16][4];
    #pragma unroll
    for (int n = 0; n < 16; n++)
        #pragma unroll
        for (int q = 0; q < 4; q++) acc2[n][q] = 0.f;

    const uint4* w1p = g_w1f + l;
    const uint4* w2p = g_w2f + l;

    for (int nb = 0; nb < 8; nb++) {
        const int j0 = nb * 64;
        const uint4* b1w = w1p + (size_t)(nb * 8 * 8 + cg * 4) * 32;
        const uint4* b2w = w2p + (size_t)(nb * 4 * 16 + cg * 8) * 32;

        // ---- GEMM1: double-buffered weight fragments ----
        float c1[8][4];
        #pragma unroll
        for (int n = 0; n < 8; n++)
            #pragma unroll
            for (int q = 0; q < 4; q++) c1[n][q] = 0.f;

        uint4 wc[4];
        #pragma unroll
        for (int i = 0; i < 4; i++) wc[i] = b1w[(size_t)i * 32];

        #pragma unroll
        for (int kt = 0; kt < 8; kt++) {
            uint32_t ah0[4], ah1[4], al0[4], al1[4];
            ldsm4(ah0, aBH[0] + kt * 32);
            ldsm4(ah1, aBH[1] + kt * 32);
            ldsm4(al0, aBL[0] + kt * 32);
            ldsm4(al1, aBL[1] + kt * 32);
            uint4 wn[4];
            if (kt < 7) {
                #pragma unroll
                for (int i = 0; i < 4; i++)
                    wn[i] = b1w[(size_t)((kt + 1) * 8 + i) * 32];
            }
            #pragma unroll
            for (int nt = 0; nt < 4; nt++) {
                mma16816(c1[nt],     ah0, wc[nt].x, wc[nt].y);
                mma16816(c1[nt],     ah0, wc[nt].z, wc[nt].w);
                mma16816(c1[nt],     al0, wc[nt].x, wc[nt].y);
                mma16816(c1[4 + nt], ah1, wc[nt].x, wc[nt].y);
                mma16816(c1[4 + nt], ah1, wc[nt].z, wc[nt].w);
                mma16816(c1[4 + nt], al1, wc[nt].x, wc[nt].y);
            }
            #pragma unroll
            for (int i = 0; i < 4; i++) wc[i] = wn[i];
        }

        // ---- bias + exact GELU -> hs ----
        #pragma unroll
        for (int mt = 0; mt < 2; mt++) {
            int row = rg * 32 + mt * 16 + (l >> 2);
            #pragma unroll
            for (int nt = 0; nt < 4; nt++) {
                int jc = cg * 32 + nt * 8 + (l & 3) * 2;
                float2 bv = *(const float2*)&b1s[j0 + jc];
                float v0 = c1[mt * 4 + nt][0] + bv.x;
                float v1 = c1[mt * 4 + nt][1] + bv.y;
                float v2 = c1[mt * 4 + nt][2] + bv.x;
                float v3 = c1[mt * 4 + nt][3] + bv.y;
                float g0 = 0.5f * v0 * (1.f + erff(v0 * 0.70710678118654752f));
                float g1 = 0.5f * v1 * (1.f + erff(v1 * 0.70710678118654752f));
                float g2 = 0.5f * v2 * (1.f + erff(v2 * 0.70710678118654752f));
                float g3 = 0.5f * v3 * (1.f + erff(v3 * 0.70710678118654752f));
                uint32_t hi, lo;
                split_pack(g0, g1, hi, lo);
                *(uint32_t*)(smraw + MS_HSH + row * 144 + jc * 2) = hi;
                *(uint32_t*)(smraw + MS_HSL + row * 144 + jc * 2) = lo;
                split_pack(g2, g3, hi, lo);
                *(uint32_t*)(smraw + MS_HSH + (row + 8) * 144 + jc * 2) = hi;
                *(uint32_t*)(smraw + MS_HSL + (row + 8) * 144 + jc * 2) = lo;
            }
        }
        __syncthreads();

        // ---- GEMM2: double-buffered in half-kt groups of 4 fragments ----
        uint4 w2c[4];
        #pragma unroll
        for (int i = 0; i < 4; i++) w2c[i] = b2w[(size_t)i * 32];

        #pragma unroll
        for (int kt2 = 0; kt2 < 4; kt2++) {
            uint32_t a0h[4], a1h[4], a0l[4], a1l[4];
            ldsm4(a0h, hBH[0] + kt2 * 32);
            ldsm4(a1h, hBH[1] + kt2 * 32);
            ldsm4(a0l, hBL[0] + kt2 * 32);
            ldsm4(a1l, hBL[1] + kt2 * 32);

            uint4 wnA[4];
            #pragma unroll
            for (int i = 0; i < 4; i++)
                wnA[i] = b2w[(size_t)(kt2 * 16 + 4 + i) * 32];

            #pragma unroll
            for (int nt = 0; nt < 4; nt++) {
                mma16816(acc2[nt],     a0h, w2c[nt].x, w2c[nt].y);
                mma16816(acc2[nt],     a0h, w2c[nt].z, w2c[nt].w);
                mma16816(acc2[nt],     a0l, w2c[nt].x, w2c[nt].y);
                mma16816(acc2[8 + nt], a1h, w2c[nt].x, w2c[nt].y);
                mma16816(acc2[8 + nt], a1h, w2c[nt].z, w2c[nt].w);
                mma16816(acc2[8 + nt], a1l, w2c[nt].x, w2c[nt].y);
            }
            uint4 wnB[4];
            if (kt2 < 3) {
                #pragma unroll
                for (int i = 0; i < 4; i++)
                    wnB[i] = b2w[(size_t)((kt2 + 1) * 16 + i) * 32];
            }
            #pragma unroll
            for (int nt = 0; nt < 4; nt++) {
                mma16816(acc2[4 + nt],  a0h, wnA[nt].x, wnA[nt].y);
                mma16816(acc2[4 + nt],  a0h, wnA[nt].z, wnA[nt].w);
                mma16816(acc2[4 + nt],  a0l, wnA[nt].x, wnA[nt].y);
                mma16816(acc2[12 + nt], a1h, wnA[nt].x, wnA[nt].y);
                mma16816(acc2[12 + nt], a1h, wnA[nt].z, wnA[nt].w);
                mma16816(acc2[12 + nt], a1l, wnA[nt].x, wnA[nt].y);
            }
            #pragma unroll
            for (int i = 0; i < 4; i++) w2c[i] = wnB[i];
        }
        __syncthreads();
    }

    // ---- epilogue: + b2 + x, NCHW store ----
    #pragma unroll
    for (int mt = 0; mt < 2; mt++) {
        #pragma unroll
        for (int half = 0; half < 2; half++) {
            int row = rg * 32 + mt * 16 + (l >> 2) + half * 8;
            size_t gpx = p0 + row;
            size_t bI = gpx / HWP, hw = gpx % HWP;
            const float* xb = x + bI * CC * HWP + hw;
            float* ob = out + bI * CC * HWP + hw;
            #pragma unroll
            for (int ntp = 0; ntp < 8; ntp++) {
                int c = cg * 64 + ((ntp < 4) ? ntp * 8 : 32 + (ntp - 4) * 8) + (l & 3) * 2;
                int ai = mt * 8 + ((ntp < 4) ? ntp : 4 + (ntp - 4));
                ob[(size_t)c * HWP] =
                    acc2[ai][half * 2] + b2s[c] + xb[(size_t)c * HWP];
                ob[(size_t)(c + 1) * HWP] =
                    acc2[ai][half * 2 + 1] + b2s[c + 1] + xb[(size_t)(c + 1) * HWP];
            }
        }
    }
}

// ---------------------------------------------------------------------------
extern "C" void kernel_launch(void* const* d_in, const int* in_sizes, int n_in,
                              void* d_out, int out_size)
{
    const float* x   = (const float*)d_in[0];
    const float* c1w = (const float*)d_in[1];
    const float* c1b = (const float*)d_in[2];
    const float* bng = (const float*)d_in[3];
    const float* bnb = (const float*)d_in[4];
    const float* bnm = (const float*)d_in[5];
    const float* bnv = (const float*)d_in[6];
    const float* c2w = (const float*)d_in[7];
    const float* c2b = (const float*)d_in[8];
    const float* lnw = (const float*)d_in[9];
    const float* lnb = (const float*)d_in[10];
    const float* w1  = (const float*)d_in[11];
    const float* b1  = (const float*)d_in[12];
    const float* w2  = (const float*)d_in[13];
    const float* b2  = (const float*)d_in[14];
    float* out = (float*)d_out;

    cudaFuncSetAttribute(kernFI, cudaFuncAttributeMaxDynamicSharedMemorySize, SMEM_F2);
    cudaFuncSetAttribute(kernM, cudaFuncAttributeMaxDynamicSharedMemorySize, SMEM_M);

    kernP<<<128, 256>>>(w1, w2);
    kernFI<<<BB * 28, 448, SMEM_F2>>>(x, c1w, c1b, bng, bnb, bnm, bnv, c2w, c2b);
    kernM<<<NPIX / 64, 128, SMEM_M>>>(x, b1, b2, lnw, lnb, out);
}